// round 4
// baseline (speedup 1.0000x reference)
#include <cuda_runtime.h>
#include <cuda_bf16.h>
#include <cstdint>
#include <cstddef>

// ---------------- problem constants ----------------
#define Bq   256
#define Nn   400
#define Hh   512
#define Ee   256
#define Vv   50000
#define OOVn 50
#define Tt   49

// output offsets (floats)
#define O_FINAL 0
#define O_H     (Bq*(Vv+OOVn))
#define O_C     (O_H + Bq*Hh)
#define O_CTE   (O_C + Bq*Hh)
#define O_SUM   (O_CTE + Bq*2*Hh)
#define O_PREVS (O_SUM + Bq*Nn)

// ---------------- scratch (static device memory; no allocs) ----------------
#define F_XCAT   0
#define F_X      (F_XCAT + 256*1280)
#define F_GATES  (F_X + 256*256)
#define F_STHAT  (F_GATES + 256*2048)
#define F_SENC   (F_STHAT + 256*1024)
#define F_SDEC   (F_SENC + 256*1024)
#define F_ET     (F_SDEC + 256*512)
#define F_AT     (F_ET + 102400)
#define F_ETD    (F_AT + 102400)
#define F_CTD    (F_ETD + 12544)
#define F_PGEN   (F_CTD + 256*512)
#define F_Z      (F_PGEN + 256)
#define F_OUTV   (F_Z + 256*2048)
#define F_LOGITS (F_OUTV + 256*512)
#define F_RMAX   (F_LOGITS + 256*50000)
#define F_RSUM   (F_RMAX + 256)
#define F_TOTAL  (F_RSUM + 256)

__device__ float g_scratch[F_TOTAL];

#define B_WH    0
#define B_WPREV (B_WH + 1024*1024)
#define B_V1    (B_WPREV + 512*512)
#define B_TOTAL (B_V1 + 50000*512)

__device__ __nv_bfloat16 g_bf[B_TOTAL];

// ---------------- helpers ----------------
__device__ __forceinline__ uint32_t pack_bf2(float x, float y) {
    __nv_bfloat162 h = __floats2bfloat162_rn(x, y);
    return *reinterpret_cast<uint32_t*>(&h);
}
__device__ __forceinline__ float sigf(float x) { return 1.f / (1.f + expf(-x)); }

// ---------------- f32 -> bf16 converter ----------------
__global__ void k_cvt_bf16(const float* __restrict__ s, __nv_bfloat16* __restrict__ d, int n) {
    for (int i = blockIdx.x * blockDim.x + threadIdx.x; i < n; i += gridDim.x * blockDim.x)
        d[i] = __float2bfloat16(s[i]);
}

// ---------------- small fp32 GEMM: C[M,N] (+)= A[M,K] @ W[N,K]^T (+ bias) ----------------
__global__ void __launch_bounds__(256) k_gemm_f32(
    const float* __restrict__ A, const float* __restrict__ W,
    const float* __restrict__ bias, float* __restrict__ C,
    int M, int N, int K, int accumulate)
{
    __shared__ float sA[16][64];
    __shared__ float sB[16][64];
    int tid = threadIdx.x;
    int tx = tid & 15, ty = tid >> 4;
    int m0 = blockIdx.x * 64, n0 = blockIdx.y * 64;
    float acc[4][4];
#pragma unroll
    for (int i = 0; i < 4; i++)
#pragma unroll
        for (int j = 0; j < 4; j++) acc[i][j] = 0.f;

    for (int k0 = 0; k0 < K; k0 += 16) {
        __syncthreads();
        for (int idx = tid; idx < 1024; idx += 256) {
            int r = idx >> 4, c = idx & 15;
            sA[c][r] = A[(size_t)(m0 + r) * K + k0 + c];
            sB[c][r] = W[(size_t)(n0 + r) * K + k0 + c];
        }
        __syncthreads();
#pragma unroll
        for (int kk = 0; kk < 16; kk++) {
            float a[4], b[4];
#pragma unroll
            for (int i = 0; i < 4; i++) { a[i] = sA[kk][ty * 4 + i]; b[i] = sB[kk][tx * 4 + i]; }
#pragma unroll
            for (int i = 0; i < 4; i++)
#pragma unroll
                for (int j = 0; j < 4; j++) acc[i][j] += a[i] * b[j];
        }
    }
#pragma unroll
    for (int i = 0; i < 4; i++) {
        int row = m0 + ty * 4 + i;
#pragma unroll
        for (int j = 0; j < 4; j++) {
            int col = n0 + tx * 4 + j;
            float val = acc[i][j];
            if (bias) val += bias[col];
            size_t o = (size_t)row * N + col;
            C[o] = accumulate ? (C[o] + val) : val;
        }
    }
}

// ---------------- fused attention-score kernel ----------------
// et[m] += sum_e v[e] * tanh( sum_k A[m,k]*W[e,k] + S[m/BDIV, e] )
// A fp32 staged to smem as bf16 (full K resident), W pre-converted bf16.
template<int K, int EDIM, int BDIV>
__global__ void __launch_bounds__(256) k_fused_score(
    const float* __restrict__ A, const __nv_bfloat16* __restrict__ Wbf,
    const float* __restrict__ S, const float* __restrict__ v,
    float* __restrict__ et)
{
    constexpr int KW = K / 2 + 4;
    extern __shared__ uint32_t smem_u32[];
    uint32_t* As = smem_u32;             // 64 * KW
    uint32_t* Bs = smem_u32 + 64 * KW;   // 64 * 36

    const int tid = threadIdx.x;
    const int m0 = blockIdx.x * 64;

    const int AW = K / 2;
    for (int idx = tid; idx < 64 * AW; idx += 256) {
        int r = idx / AW, c = idx - r * AW;
        float2 f = reinterpret_cast<const float2*>(A + (size_t)(m0 + r) * K)[c];
        As[r * KW + c] = pack_bf2(f.x, f.y);
    }

    const uint32_t* Wb32 = reinterpret_cast<const uint32_t*>(Wbf);
    int warp = tid >> 5, lane = tid & 31;
    int wm = warp & 3, wn = warp >> 2;   // 4 M-warps x 2 N-warps
    int g = lane >> 2, tg = lane & 3;
    int row_lo = m0 + wm * 16 + g;
    int row_hi = row_lo + 8;
    const float* S_lo = S + (size_t)(row_lo / BDIV) * EDIM;
    const float* S_hi = S + (size_t)(row_hi / BDIV) * EDIM;
    float p_lo = 0.f, p_hi = 0.f;

    for (int e0 = 0; e0 < EDIM; e0 += 64) {
        float acc[4][4];
#pragma unroll
        for (int i = 0; i < 4; i++)
#pragma unroll
            for (int j = 0; j < 4; j++) acc[i][j] = 0.f;

        for (int k0 = 0; k0 < K; k0 += 64) {
            __syncthreads();
            for (int idx = tid; idx < 64 * 32; idx += 256) {
                int r = idx >> 5, c = idx & 31;
                Bs[r * 36 + c] = Wb32[(size_t)(e0 + r) * (K / 2) + (k0 >> 1) + c];
            }
            __syncthreads();
#pragma unroll
            for (int kk = 0; kk < 4; kk++) {
                int wb = (k0 >> 1) + kk * 8;
                uint32_t a0 = As[(wm * 16 + g) * KW + wb + tg];
                uint32_t a1 = As[(wm * 16 + g + 8) * KW + wb + tg];
                uint32_t a2 = As[(wm * 16 + g) * KW + wb + 4 + tg];
                uint32_t a3 = As[(wm * 16 + g + 8) * KW + wb + 4 + tg];
#pragma unroll
                for (int nt = 0; nt < 4; nt++) {
                    int brow = wn * 32 + nt * 8 + g;
                    uint32_t b0 = Bs[brow * 36 + kk * 8 + tg];
                    uint32_t b1 = Bs[brow * 36 + kk * 8 + 4 + tg];
                    asm volatile(
                        "mma.sync.aligned.m16n8k16.row.col.f32.bf16.bf16.f32 "
                        "{%0,%1,%2,%3}, {%4,%5,%6,%7}, {%8,%9}, {%0,%1,%2,%3};\n"
                        : "+f"(acc[nt][0]), "+f"(acc[nt][1]), "+f"(acc[nt][2]), "+f"(acc[nt][3])
                        : "r"(a0), "r"(a1), "r"(a2), "r"(a3), "r"(b0), "r"(b1));
                }
            }
        }
#pragma unroll
        for (int nt = 0; nt < 4; nt++) {
            int e = e0 + wn * 32 + nt * 8 + tg * 2;
            float v0 = v[e], v1 = v[e + 1];
            p_lo += v0 * tanhf(acc[nt][0] + S_lo[e]) + v1 * tanhf(acc[nt][1] + S_lo[e + 1]);
            p_hi += v0 * tanhf(acc[nt][2] + S_hi[e]) + v1 * tanhf(acc[nt][3] + S_hi[e + 1]);
        }
    }
    p_lo += __shfl_xor_sync(0xffffffffu, p_lo, 1);
    p_lo += __shfl_xor_sync(0xffffffffu, p_lo, 2);
    p_hi += __shfl_xor_sync(0xffffffffu, p_hi, 1);
    p_hi += __shfl_xor_sync(0xffffffffu, p_hi, 2);
    if (tg == 0) {
        atomicAdd(&et[row_lo], p_lo);
        atomicAdd(&et[row_hi], p_hi);
    }
}

// ---------------- logits GEMM (bf16 mma): C[256,N] = A[256,512] @ W[N,512]^T + bias ----------------
__global__ void __launch_bounds__(256) k_gemm_mma_logits(
    const float* __restrict__ A, const __nv_bfloat16* __restrict__ Wbf,
    const float* __restrict__ bias, float* __restrict__ C, int N)
{
    constexpr int K = 512;
    constexpr int KW = K / 2 + 4;
    extern __shared__ uint32_t smem_u32[];
    uint32_t* As = smem_u32;
    uint32_t* Bs = smem_u32 + 64 * KW;
    int tid = threadIdx.x;
    int m0 = blockIdx.x * 64;
    int n0 = blockIdx.y * 64;

    for (int idx = tid; idx < 64 * (K / 2); idx += 256) {
        int r = idx / (K / 2), c = idx - r * (K / 2);
        float2 f = reinterpret_cast<const float2*>(A + (size_t)(m0 + r) * K)[c];
        As[r * KW + c] = pack_bf2(f.x, f.y);
    }
    const uint32_t* Wb32 = reinterpret_cast<const uint32_t*>(Wbf);
    int warp = tid >> 5, lane = tid & 31;
    int wm = warp & 3, wn = warp >> 2;
    int g = lane >> 2, tg = lane & 3;

    float acc[4][4];
#pragma unroll
    for (int i = 0; i < 4; i++)
#pragma unroll
        for (int j = 0; j < 4; j++) acc[i][j] = 0.f;

    for (int k0 = 0; k0 < K; k0 += 64) {
        __syncthreads();
        for (int idx = tid; idx < 64 * 32; idx += 256) {
            int r = idx >> 5, c = idx & 31;
            int n = n0 + r;
            Bs[r * 36 + c] = (n < N) ? Wb32[(size_t)n * (K / 2) + (k0 >> 1) + c] : 0u;
        }
        __syncthreads();
#pragma unroll
        for (int kk = 0; kk < 4; kk++) {
            int wb = (k0 >> 1) + kk * 8;
            uint32_t a0 = As[(wm * 16 + g) * KW + wb + tg];
            uint32_t a1 = As[(wm * 16 + g + 8) * KW + wb + tg];
            uint32_t a2 = As[(wm * 16 + g) * KW + wb + 4 + tg];
            uint32_t a3 = As[(wm * 16 + g + 8) * KW + wb + 4 + tg];
#pragma unroll
            for (int nt = 0; nt < 4; nt++) {
                int brow = wn * 32 + nt * 8 + g;
                uint32_t b0 = Bs[brow * 36 + kk * 8 + tg];
                uint32_t b1 = Bs[brow * 36 + kk * 8 + 4 + tg];
                asm volatile(
                    "mma.sync.aligned.m16n8k16.row.col.f32.bf16.bf16.f32 "
                    "{%0,%1,%2,%3}, {%4,%5,%6,%7}, {%8,%9}, {%0,%1,%2,%3};\n"
                    : "+f"(acc[nt][0]), "+f"(acc[nt][1]), "+f"(acc[nt][2]), "+f"(acc[nt][3])
                    : "r"(a0), "r"(a1), "r"(a2), "r"(a3), "r"(b0), "r"(b1));
            }
        }
    }
    int row_lo = m0 + wm * 16 + g;
    int row_hi = row_lo + 8;
#pragma unroll
    for (int nt = 0; nt < 4; nt++) {
        int col = n0 + wn * 32 + nt * 8 + tg * 2;
        if (col < N) {
            float b0v = bias[col], b1v = bias[col + 1];
            *reinterpret_cast<float2*>(C + (size_t)row_lo * N + col) =
                make_float2(acc[nt][0] + b0v, acc[nt][1] + b1v);
            *reinterpret_cast<float2*>(C + (size_t)row_hi * N + col) =
                make_float2(acc[nt][2] + b0v, acc[nt][3] + b1v);
        }
    }
}

// ---------------- elementwise / reduction kernels ----------------
__global__ void k_build_xcat(const float* __restrict__ x_t, const float* __restrict__ ct_e,
                             float* __restrict__ xcat) {
    int idx = blockIdx.x * blockDim.x + threadIdx.x;
    int b = idx / 1280, j = idx - b * 1280;
    xcat[idx] = (j < Ee) ? x_t[b * Ee + j] : ct_e[b * 1024 + (j - Ee)];
}

__global__ void k_lstm_cell(const float* __restrict__ gates, const float* __restrict__ dec_c,
                            float* __restrict__ h_out, float* __restrict__ c_out,
                            float* __restrict__ sthat) {
    int idx = blockIdx.x * blockDim.x + threadIdx.x;
    int b = idx >> 9, j = idx & 511;
    const float* gr = gates + (size_t)b * 2048;
    float ig = sigf(gr[j]);
    float fg = sigf(gr[512 + j]);
    float gg = tanhf(gr[1024 + j]);
    float og = sigf(gr[1536 + j]);
    float c = fg * dec_c[idx] + ig * gg;
    float h = og * tanhf(c);
    h_out[idx] = h;
    c_out[idx] = c;
    sthat[(size_t)b * 1024 + j] = h;
    sthat[(size_t)b * 1024 + 512 + j] = c;
}

__global__ void k_enc_attn_norm(const float* __restrict__ et, const float* __restrict__ sum_t,
                                const float* __restrict__ mask, float* __restrict__ at,
                                float* __restrict__ sum_new) {
    int b = blockIdx.x;
    __shared__ float red[128];
    float local = 0.f;
    for (int n = threadIdx.x; n < Nn; n += 128) {
        float e = expf(et[b * Nn + n]);
        float st = sum_t[b * Nn + n];
        sum_new[b * Nn + n] = st + e;
        float a = (e / st) * mask[b * Nn + n];
        at[b * Nn + n] = a;
        local += a;
    }
    red[threadIdx.x] = local;
    __syncthreads();
    for (int s = 64; s > 0; s >>= 1) {
        if (threadIdx.x < s) red[threadIdx.x] += red[threadIdx.x + s];
        __syncthreads();
    }
    float inv = 1.f / red[0];
    for (int n = threadIdx.x; n < Nn; n += 128) at[b * Nn + n] *= inv;
}

__global__ void k_ctx_enc(const float* __restrict__ at, const float* __restrict__ enc,
                          float* __restrict__ ct) {
    int b = blockIdx.x, chunk = blockIdx.y;            // grid (256,4), 256 thr
    __shared__ float a_s[100];
    int n_start = chunk * 100;
    if (threadIdx.x < 100) a_s[threadIdx.x] = at[b * Nn + n_start + threadIdx.x];
    __syncthreads();
    float4 acc = make_float4(0.f, 0.f, 0.f, 0.f);
    int d4 = threadIdx.x;
    const float4* e4 = reinterpret_cast<const float4*>(enc + ((size_t)b * Nn + n_start) * 1024);
#pragma unroll 4
    for (int n = 0; n < 100; n++) {
        float4 x = e4[(size_t)n * 256 + d4];
        float a = a_s[n];
        acc.x += a * x.x; acc.y += a * x.y; acc.z += a * x.z; acc.w += a * x.w;
    }
    float* o = ct + (size_t)b * 1024 + d4 * 4;
    atomicAdd(o + 0, acc.x); atomicAdd(o + 1, acc.y);
    atomicAdd(o + 2, acc.z); atomicAdd(o + 3, acc.w);
}

__global__ void k_dec_attn(const float* __restrict__ etd, const float* __restrict__ prev_s,
                           float* __restrict__ ctd) {
    int b = blockIdx.x;
    __shared__ float a_s[Tt];
    if (threadIdx.x == 0) {
        float m = -1e30f;
        for (int t = 0; t < Tt; t++) m = fmaxf(m, etd[b * Tt + t]);
        float s = 0.f;
        for (int t = 0; t < Tt; t++) { float e = expf(etd[b * Tt + t] - m); a_s[t] = e; s += e; }
        float inv = 1.f / s;
        for (int t = 0; t < Tt; t++) a_s[t] *= inv;
    }
    __syncthreads();
    for (int h = threadIdx.x; h < Hh; h += 256) {
        float acc = 0.f;
        for (int t = 0; t < Tt; t++) acc += a_s[t] * prev_s[((size_t)b * Tt + t) * Hh + h];
        ctd[b * Hh + h] = acc;
    }
}

__global__ void k_pgen(const float* __restrict__ cte, const float* __restrict__ ctd,
                       const float* __restrict__ sthat, const float* __restrict__ x,
                       const float* __restrict__ pw, const float* __restrict__ pb,
                       float* __restrict__ pgen) {
    int b = blockIdx.x; int t = threadIdx.x;
    float acc = 0.f;
    for (int j = t; j < 1024; j += 128) acc += cte[b * 1024 + j] * pw[j];
    for (int j = t; j < 512;  j += 128) acc += ctd[b * 512 + j] * pw[1024 + j];
    for (int j = t; j < 1024; j += 128) acc += sthat[b * 1024 + j] * pw[1536 + j];
    for (int j = t; j < 256;  j += 128) acc += x[b * 256 + j] * pw[2560 + j];
    __shared__ float red[128];
    red[t] = acc;
    __syncthreads();
    for (int s = 64; s > 0; s >>= 1) { if (t < s) red[t] += red[t + s]; __syncthreads(); }
    if (t == 0) pgen[b] = sigf(red[0] + pb[0]);
}

__global__ void k_build_z(const float* __restrict__ h, const float* __restrict__ cte,
                          const float* __restrict__ ctd, float* __restrict__ z) {
    int idx = blockIdx.x * blockDim.x + threadIdx.x;
    int b = idx >> 11, j = idx & 2047;
    float v;
    if (j < 512)       v = h[b * 512 + j];
    else if (j < 1536) v = cte[b * 1024 + (j - 512)];
    else               v = ctd[b * 512 + (j - 1536)];
    z[idx] = v;
}

__global__ void k_softmax_stats(const float* __restrict__ logits,
                                float* __restrict__ rmax, float* __restrict__ rsum) {
    int b = blockIdx.x;
    __shared__ float red[256];
    float m = -1e30f;
    for (int v = threadIdx.x; v < Vv; v += 256) m = fmaxf(m, logits[(size_t)b * Vv + v]);
    red[threadIdx.x] = m;
    __syncthreads();
    for (int s = 128; s > 0; s >>= 1) {
        if (threadIdx.x < s) red[threadIdx.x] = fmaxf(red[threadIdx.x], red[threadIdx.x + s]);
        __syncthreads();
    }
    float mm = red[0];
    __syncthreads();
    float sum = 0.f;
    for (int v = threadIdx.x; v < Vv; v += 256) sum += expf(logits[(size_t)b * Vv + v] - mm);
    red[threadIdx.x] = sum;
    __syncthreads();
    for (int s = 128; s > 0; s >>= 1) {
        if (threadIdx.x < s) red[threadIdx.x] += red[threadIdx.x + s];
        __syncthreads();
    }
    if (threadIdx.x == 0) { rmax[b] = mm; rsum[b] = red[0]; }
}

__global__ void k_final_vocab(const float* __restrict__ logits, const float* __restrict__ rmax,
                              const float* __restrict__ rsum, const float* __restrict__ pgen,
                              const float* __restrict__ extra, float* __restrict__ out) {
    int idx = blockIdx.x * blockDim.x + threadIdx.x;
    if (idx >= Bq * (Vv + OOVn)) return;
    int b = idx / (Vv + OOVn);
    int v = idx - b * (Vv + OOVn);
    float val;
    if (v < Vv) val = pgen[b] * expf(logits[(size_t)b * Vv + v] - rmax[b]) / rsum[b];
    else        val = extra[(size_t)b * OOVn + (v - Vv)];
    out[idx] = val;
}

__global__ void k_scatter(const int* __restrict__ idxs, const float* __restrict__ at,
                          const float* __restrict__ pgen, float* __restrict__ out) {
    int i = blockIdx.x * blockDim.x + threadIdx.x;
    if (i >= Bq * Nn) return;
    int b = i / Nn;
    int v = idxs[i];
    atomicAdd(&out[(size_t)b * (Vv + OOVn) + v], (1.f - pgen[b]) * at[i]);
}

__global__ void k_build_prev_s(const float* __restrict__ prev_s, const float* __restrict__ h,
                               float* __restrict__ out) {
    int i = blockIdx.x * blockDim.x + threadIdx.x;
    if (i >= Bq * (Tt + 1) * Hh) return;
    int b = i / ((Tt + 1) * Hh);
    int r = i - b * ((Tt + 1) * Hh);
    int t = r / Hh, hh = r - t * Hh;
    out[i] = (t < Tt) ? prev_s[((size_t)b * Tt + t) * Hh + hh] : h[b * Hh + hh];
}

// ---------------- host launcher ----------------
extern "C" void kernel_launch(void* const* d_in, const int* in_sizes, int n_in,
                              void* d_out, int out_size) {
    const float* x_t          = (const float*)d_in[0];
    const float* dec_h        = (const float*)d_in[1];
    const float* dec_c        = (const float*)d_in[2];
    const float* enc_out      = (const float*)d_in[3];
    const float* enc_mask     = (const float*)d_in[4];
    const float* ct_e         = (const float*)d_in[5];
    const float* extra_zeros  = (const float*)d_in[6];
    const int*   ext_vocab    = (const int*)d_in[7];
    const float* sum_temporal = (const float*)d_in[8];
    const float* prev_s       = (const float*)d_in[9];
    const float* x_input_w    = (const float*)d_in[10];
    const float* x_input_b    = (const float*)d_in[11];
    const float* lstm_w_ih    = (const float*)d_in[12];
    const float* lstm_w_hh    = (const float*)d_in[13];
    const float* lstm_b_ih    = (const float*)d_in[14];
    const float* lstm_b_hh    = (const float*)d_in[15];
    const float* pgen_w       = (const float*)d_in[16];
    const float* pgen_b       = (const float*)d_in[17];
    const float* V_w          = (const float*)d_in[18];
    const float* V_b          = (const float*)d_in[19];
    const float* V1_w         = (const float*)d_in[20];
    const float* V1_b         = (const float*)d_in[21];
    const float* Wh_w         = (const float*)d_in[22];
    const float* Ws_w         = (const float*)d_in[23];
    const float* Ws_b         = (const float*)d_in[24];
    const float* v_w          = (const float*)d_in[25];
    const float* Wprev_w      = (const float*)d_in[26];
    const float* Wsd_w        = (const float*)d_in[27];
    const float* Wsd_b        = (const float*)d_in[28];
    const float* vd_w         = (const float*)d_in[29];

    float* out = (float*)d_out;
    float* o_final = out + O_FINAL;
    float* o_h     = out + O_H;
    float* o_c     = out + O_C;
    float* o_cte   = out + O_CTE;
    float* o_sum   = out + O_SUM;
    float* o_prevs = out + O_PREVS;

    void* p = nullptr;
    cudaGetSymbolAddress(&p, g_scratch);
    float* S = (float*)p;
    cudaGetSymbolAddress(&p, g_bf);
    __nv_bfloat16* BF = (__nv_bfloat16*)p;

    float* s_xcat  = S + F_XCAT;
    float* s_x     = S + F_X;
    float* s_gates = S + F_GATES;
    float* s_sthat = S + F_STHAT;
    float* s_senc  = S + F_SENC;
    float* s_sdec  = S + F_SDEC;
    float* s_et    = S + F_ET;
    float* s_at    = S + F_AT;
    float* s_etd   = S + F_ETD;
    float* s_ctd   = S + F_CTD;
    float* s_pgen  = S + F_PGEN;
    float* s_z     = S + F_Z;
    float* s_outv  = S + F_OUTV;
    float* s_log   = S + F_LOGITS;
    float* s_rmax  = S + F_RMAX;
    float* s_rsum  = S + F_RSUM;

    __nv_bfloat16* bf_wh    = BF + B_WH;
    __nv_bfloat16* bf_wprev = BF + B_WPREV;
    __nv_bfloat16* bf_v1    = BF + B_V1;

    const int SMEM_ENC = (64 * (1024 / 2 + 4) + 64 * 36) * 4;   // 141312
    const int SMEM_512 = (64 * (512 / 2 + 4) + 64 * 36) * 4;    // 75776
    cudaFuncSetAttribute(k_fused_score<1024, 1024, 400>,
                         cudaFuncAttributeMaxDynamicSharedMemorySize, SMEM_ENC);
    cudaFuncSetAttribute(k_fused_score<512, 512, 49>,
                         cudaFuncAttributeMaxDynamicSharedMemorySize, SMEM_512);
    cudaFuncSetAttribute(k_gemm_mma_logits,
                         cudaFuncAttributeMaxDynamicSharedMemorySize, SMEM_512);

    // 0) weight conversions to bf16
    k_cvt_bf16<<<2048, 256>>>(Wh_w, bf_wh, 1024 * 1024);
    k_cvt_bf16<<<1024, 256>>>(Wprev_w, bf_wprev, 512 * 512);
    k_cvt_bf16<<<4096, 256>>>(V1_w, bf_v1, Vv * 512);

    // 1) x = [x_t | ct_e] @ x_input_w^T + b
    k_build_xcat<<<(256 * 1280) / 256, 256>>>(x_t, ct_e, s_xcat);
    k_gemm_f32<<<dim3(4, 4), 256>>>(s_xcat, x_input_w, x_input_b, s_x, 256, 256, 1280, 0);

    // 2) LSTM gates + cell
    k_gemm_f32<<<dim3(4, 32), 256>>>(s_x, lstm_w_ih, lstm_b_ih, s_gates, 256, 2048, 256, 0);
    k_gemm_f32<<<dim3(4, 32), 256>>>(dec_h, lstm_w_hh, lstm_b_hh, s_gates, 256, 2048, 512, 1);
    k_lstm_cell<<<512, 256>>>(s_gates, dec_c, o_h, o_c, s_sthat);

    // 3) encoder attention
    k_gemm_f32<<<dim3(4, 16), 256>>>(s_sthat, Ws_w, Ws_b, s_senc, 256, 1024, 1024, 0);
    cudaMemsetAsync(s_et, 0, 102400 * sizeof(float));
    k_fused_score<1024, 1024, 400><<<1600, 256, SMEM_ENC>>>(enc_out, bf_wh, s_senc, v_w, s_et);
    k_enc_attn_norm<<<256, 128>>>(s_et, sum_temporal, enc_mask, s_at, o_sum);
    cudaMemsetAsync(o_cte, 0, 262144 * sizeof(float));
    k_ctx_enc<<<dim3(256, 4), 256>>>(s_at, enc_out, o_cte);

    // 4) decoder intra-attention
    k_gemm_f32<<<dim3(4, 8), 256>>>(o_h, Wsd_w, Wsd_b, s_sdec, 256, 512, 512, 0);
    cudaMemsetAsync(s_etd, 0, 12544 * sizeof(float));
    k_fused_score<512, 512, 49><<<196, 256, SMEM_512>>>(prev_s, bf_wprev, s_sdec, vd_w, s_etd);
    k_dec_attn<<<256, 256>>>(s_etd, prev_s, s_ctd);

    // 5) pointer-generator head
    k_pgen<<<256, 128>>>(o_cte, s_ctd, s_sthat, s_x, pgen_w, pgen_b, s_pgen);
    k_build_z<<<(256 * 2048) / 256, 256>>>(o_h, o_cte, s_ctd, s_z);
    k_gemm_f32<<<dim3(4, 8), 256>>>(s_z, V_w, V_b, s_outv, 256, 512, 2048, 0);
    k_gemm_mma_logits<<<dim3(4, 782), 256, SMEM_512>>>(s_outv, bf_v1, V1_b, s_log, Vv);
    k_softmax_stats<<<256, 256>>>(s_log, s_rmax, s_rsum);

    // 6) final distribution
    k_final_vocab<<<(Bq * (Vv + OOVn) + 255) / 256, 256>>>(s_log, s_rmax, s_rsum, s_pgen,
                                                           extra_zeros, o_final);
    k_scatter<<<(Bq * Nn + 255) / 256, 256>>>(ext_vocab, s_at, s_pgen, o_final);

    // 7) prev_s_new
    k_build_prev_s<<<(Bq * (Tt + 1) * Hh + 255) / 256, 256>>>(prev_s, o_h, o_prevs);
}

// round 6
// speedup vs baseline: 1.4157x; 1.4157x over previous
#include <cuda_runtime.h>
#include <cuda_bf16.h>
#include <cstdint>
#include <cstddef>

// ---------------- problem constants ----------------
#define Bq   256
#define Nn   400
#define Hh   512
#define Ee   256
#define Vv   50000
#define OOVn 50
#define Tt   49

// output offsets (floats)
#define O_FINAL 0
#define O_H     (Bq*(Vv+OOVn))
#define O_C     (O_H + Bq*Hh)
#define O_CTE   (O_C + Bq*Hh)
#define O_SUM   (O_CTE + Bq*2*Hh)
#define O_PREVS (O_SUM + Bq*Nn)

// ---------------- scratch (static device memory; no allocs) ----------------
#define F_XCAT   0
#define F_X      (F_XCAT + 256*1280)
#define F_GATES  (F_X + 256*256)
#define F_STHAT  (F_GATES + 256*2048)
#define F_SENC   (F_STHAT + 256*1024)
#define F_SDEC   (F_SENC + 256*1024)
#define F_ET     (F_SDEC + 256*512)
#define F_AT     (F_ET + 102400)
#define F_ETD    (F_AT + 102400)
#define F_CTD    (F_ETD + 12544)
#define F_PGEN   (F_CTD + 256*512)
#define F_Z      (F_PGEN + 256)
#define F_OUTV   (F_Z + 256*2048)
#define F_LOGITS (F_OUTV + 256*512)
#define F_RMAX   (F_LOGITS + 256*50000)
#define F_RSUM   (F_RMAX + 256)
#define F_TOTAL  (F_RSUM + 256)

__device__ float g_scratch[F_TOTAL];

#define B_WH    0
#define B_WPREV (B_WH + 1024*1024)
#define B_V1    (B_WPREV + 512*512)
#define B_TOTAL (B_V1 + 50000*512)

__device__ __nv_bfloat16 g_bf[B_TOTAL];

// ---------------- helpers ----------------
__device__ __forceinline__ uint32_t pack_bf2(float x, float y) {
    __nv_bfloat162 h = __floats2bfloat162_rn(x, y);
    return *reinterpret_cast<uint32_t*>(&h);
}
__device__ __forceinline__ float sigf(float x) { return 1.f / (1.f + expf(-x)); }
__device__ __forceinline__ float tanh_fast(float x) {
    float y;
    asm("tanh.approx.f32 %0, %1;" : "=f"(y) : "f"(x));
    return y;
}
__device__ __forceinline__ void cp_async16(uint32_t dst, const void* src) {
    asm volatile("cp.async.cg.shared.global [%0], [%1], 16;\n" :: "r"(dst), "l"(src));
}
__device__ __forceinline__ void cp_commit() { asm volatile("cp.async.commit_group;\n"); }
__device__ __forceinline__ void cp_wait1() { asm volatile("cp.async.wait_group 1;\n"); }
__device__ __forceinline__ void cp_wait0() { asm volatile("cp.async.wait_group 0;\n"); }

// ---------------- f32 -> bf16 converter ----------------
__global__ void k_cvt_bf16(const float* __restrict__ s, __nv_bfloat16* __restrict__ d, int n) {
    for (int i = blockIdx.x * blockDim.x + threadIdx.x; i < n; i += gridDim.x * blockDim.x)
        d[i] = __float2bfloat16(s[i]);
}

// ---------------- small fp32 GEMM: C[M,N] (+)= A[M,K] @ W[N,K]^T (+ bias) ----------------
__global__ void __launch_bounds__(256) k_gemm_f32(
    const float* __restrict__ A, const float* __restrict__ W,
    const float* __restrict__ bias, float* __restrict__ C,
    int M, int N, int K, int accumulate)
{
    __shared__ float sA[16][64];
    __shared__ float sB[16][64];
    int tid = threadIdx.x;
    int tx = tid & 15, ty = tid >> 4;
    int m0 = blockIdx.x * 64, n0 = blockIdx.y * 64;
    float acc[4][4];
#pragma unroll
    for (int i = 0; i < 4; i++)
#pragma unroll
        for (int j = 0; j < 4; j++) acc[i][j] = 0.f;

    for (int k0 = 0; k0 < K; k0 += 16) {
        __syncthreads();
        for (int idx = tid; idx < 1024; idx += 256) {
            int r = idx >> 4, c = idx & 15;
            sA[c][r] = A[(size_t)(m0 + r) * K + k0 + c];
            sB[c][r] = W[(size_t)(n0 + r) * K + k0 + c];
        }
        __syncthreads();
#pragma unroll
        for (int kk = 0; kk < 16; kk++) {
            float a[4], b[4];
#pragma unroll
            for (int i = 0; i < 4; i++) { a[i] = sA[kk][ty * 4 + i]; b[i] = sB[kk][tx * 4 + i]; }
#pragma unroll
            for (int i = 0; i < 4; i++)
#pragma unroll
                for (int j = 0; j < 4; j++) acc[i][j] += a[i] * b[j];
        }
    }
#pragma unroll
    for (int i = 0; i < 4; i++) {
        int row = m0 + ty * 4 + i;
#pragma unroll
        for (int j = 0; j < 4; j++) {
            int col = n0 + tx * 4 + j;
            float val = acc[i][j];
            if (bias) val += bias[col];
            size_t o = (size_t)row * N + col;
            C[o] = accumulate ? (C[o] + val) : val;
        }
    }
}

// ---------------- fused attention-score kernel (cp.async double-buffered) ----------------
// et[m] += sum_e v[e] * tanh( sum_k A[m,k]*W[e,k] + S[m/BDIV, e] )
// A fp32 staged once to smem as bf16 (full K resident).
// B (W) streamed in tiles of 64 e-rows x 128 k, double buffered via cp.async.
template<int K, int EDIM, int BDIV>
__global__ void __launch_bounds__(256) k_fused_score(
    const float* __restrict__ A, const __nv_bfloat16* __restrict__ Wbf,
    const float* __restrict__ S, const float* __restrict__ v,
    float* __restrict__ et)
{
    constexpr int KW = K / 2 + 4;        // padded A row width in u32
    constexpr int KIT = K / 128;         // k-chunks per e-chunk
    constexpr int ECH = EDIM / 64;       // e-chunks
    constexpr int NIT = KIT * ECH;       // total tile iterations
    constexpr int BROW = 68;             // B tile row width in u32 (64 data + 4 pad)
    constexpr int BUFW = 64 * BROW;      // one B buffer in u32

    extern __shared__ uint32_t smem_u32[];
    uint32_t* As = smem_u32;                    // 64 * KW
    uint32_t* Bs = smem_u32 + 64 * KW;          // 2 * BUFW

    const int tid = threadIdx.x;
    const int m0 = blockIdx.x * 64;

    // stage A tile (64 rows x K fp32) as bf16, full K resident
    const int AW = K / 2;
    for (int idx = tid; idx < 64 * AW; idx += 256) {
        int r = idx / AW, c = idx - r * AW;
        float2 f = reinterpret_cast<const float2*>(A + (size_t)(m0 + r) * K)[c];
        As[r * KW + c] = pack_bf2(f.x, f.y);
    }

    // smem byte base of B buffers for cp.async
    uint32_t bs_base;
    {
        void* gp = (void*)Bs;
        bs_base = (uint32_t)__cvta_generic_to_shared(gp);
    }
    const char* Wbytes = reinterpret_cast<const char*>(Wbf);

    // tile issue: tile t covers e0 = (t/KIT)*64, k0 = (t%KIT)*128
    auto issue_tile = [&](int t) {
        int e0 = (t / KIT) * 64;
        int k0 = (t - (t / KIT) * KIT) * 128;
        uint32_t dstb = bs_base + (uint32_t)(t & 1) * (BUFW * 4);
        // 64 rows x 16 chunks of 16B
        for (int idx = tid; idx < 1024; idx += 256) {
            int r = idx >> 4, c = idx & 15;
            cp_async16(dstb + r * (BROW * 4) + c * 16,
                       Wbytes + ((size_t)(e0 + r) * K + k0 + c * 8) * 2);
        }
        cp_commit();
    };

    const int warp = tid >> 5, lane = tid & 31;
    const int wm = warp & 3, wn = warp >> 2;   // 4 M-warps x 2 N-warps
    const int g = lane >> 2, tg = lane & 3;
    const int row_lo = m0 + wm * 16 + g;
    const int row_hi = row_lo + 8;
    const float* S_lo = S + (size_t)(row_lo / BDIV) * EDIM;
    const float* S_hi = S + (size_t)(row_hi / BDIV) * EDIM;
    float p_lo = 0.f, p_hi = 0.f;

    // prologue: prefetch tile 0
    issue_tile(0);

    int it = 0;
    for (int e0idx = 0; e0idx < ECH; e0idx++) {
        float acc[4][4];
#pragma unroll
        for (int i = 0; i < 4; i++)
#pragma unroll
            for (int j = 0; j < 4; j++) acc[i][j] = 0.f;

        for (int k0idx = 0; k0idx < KIT; k0idx++) {
            int nxt = it + 1;
            if (nxt < NIT) { issue_tile(nxt); cp_wait1(); }
            else           { cp_wait0(); }
            __syncthreads();

            const uint32_t* Bb = Bs + (it & 1) * BUFW;
            const int k0 = k0idx * 128;
#pragma unroll
            for (int kk = 0; kk < 8; kk++) {
                int wb = (k0 >> 1) + kk * 8;
                uint32_t a0 = As[(wm * 16 + g) * KW + wb + tg];
                uint32_t a1 = As[(wm * 16 + g + 8) * KW + wb + tg];
                uint32_t a2 = As[(wm * 16 + g) * KW + wb + 4 + tg];
                uint32_t a3 = As[(wm * 16 + g + 8) * KW + wb + 4 + tg];
#pragma unroll
                for (int nt = 0; nt < 4; nt++) {
                    int brow = wn * 32 + nt * 8 + g;
                    uint32_t b0 = Bb[brow * BROW + kk * 8 + tg];
                    uint32_t b1 = Bb[brow * BROW + kk * 8 + 4 + tg];
                    asm volatile(
                        "mma.sync.aligned.m16n8k16.row.col.f32.bf16.bf16.f32 "
                        "{%0,%1,%2,%3}, {%4,%5,%6,%7}, {%8,%9}, {%0,%1,%2,%3};\n"
                        : "+f"(acc[nt][0]), "+f"(acc[nt][1]), "+f"(acc[nt][2]), "+f"(acc[nt][3])
                        : "r"(a0), "r"(a1), "r"(a2), "r"(a3), "r"(b0), "r"(b1));
                }
            }
            __syncthreads();
            it++;
        }

        // epilogue for this e-chunk: tanh + v-weighted reduce (registers only)
        const int e0 = e0idx * 64;
#pragma unroll
        for (int nt = 0; nt < 4; nt++) {
            int e = e0 + wn * 32 + nt * 8 + tg * 2;
            float v0 = v[e], v1 = v[e + 1];
            p_lo += v0 * tanh_fast(acc[nt][0] + S_lo[e]) + v1 * tanh_fast(acc[nt][1] + S_lo[e + 1]);
            p_hi += v0 * tanh_fast(acc[nt][2] + S_hi[e]) + v1 * tanh_fast(acc[nt][3] + S_hi[e + 1]);
        }
    }

    p_lo += __shfl_xor_sync(0xffffffffu, p_lo, 1);
    p_lo += __shfl_xor_sync(0xffffffffu, p_lo, 2);
    p_hi += __shfl_xor_sync(0xffffffffu, p_hi, 1);
    p_hi += __shfl_xor_sync(0xffffffffu, p_hi, 2);
    if (tg == 0) {
        atomicAdd(&et[row_lo], p_lo);
        atomicAdd(&et[row_hi], p_hi);
    }
}

// ---------------- logits GEMM (bf16 mma): C[256,N] = A[256,512] @ W[N,512]^T + bias ----------------
__global__ void __launch_bounds__(256) k_gemm_mma_logits(
    const float* __restrict__ A, const __nv_bfloat16* __restrict__ Wbf,
    const float* __restrict__ bias, float* __restrict__ C, int N)
{
    constexpr int K = 512;
    constexpr int KW = K / 2 + 4;
    extern __shared__ uint32_t smem_u32[];
    uint32_t* As = smem_u32;
    uint32_t* Bs = smem_u32 + 64 * KW;
    int tid = threadIdx.x;
    int m0 = blockIdx.x * 64;
    int n0 = blockIdx.y * 64;

    for (int idx = tid; idx < 64 * (K / 2); idx += 256) {
        int r = idx / (K / 2), c = idx - r * (K / 2);
        float2 f = reinterpret_cast<const float2*>(A + (size_t)(m0 + r) * K)[c];
        As[r * KW + c] = pack_bf2(f.x, f.y);
    }
    const uint32_t* Wb32 = reinterpret_cast<const uint32_t*>(Wbf);
    int warp = tid >> 5, lane = tid & 31;
    int wm = warp & 3, wn = warp >> 2;
    int g = lane >> 2, tg = lane & 3;

    float acc[4][4];
#pragma unroll
    for (int i = 0; i < 4; i++)
#pragma unroll
        for (int j = 0; j < 4; j++) acc[i][j] = 0.f;

    for (int k0 = 0; k0 < K; k0 += 64) {
        __syncthreads();
        for (int idx = tid; idx < 64 * 32; idx += 256) {
            int r = idx >> 5, c = idx & 31;
            int n = n0 + r;
            Bs[r * 36 + c] = (n < N) ? Wb32[(size_t)n * (K / 2) + (k0 >> 1) + c] : 0u;
        }
        __syncthreads();
#pragma unroll
        for (int kk = 0; kk < 4; kk++) {
            int wb = (k0 >> 1) + kk * 8;
            uint32_t a0 = As[(wm * 16 + g) * KW + wb + tg];
            uint32_t a1 = As[(wm * 16 + g + 8) * KW + wb + tg];
            uint32_t a2 = As[(wm * 16 + g) * KW + wb + 4 + tg];
            uint32_t a3 = As[(wm * 16 + g + 8) * KW + wb + 4 + tg];
#pragma unroll
            for (int nt = 0; nt < 4; nt++) {
                int brow = wn * 32 + nt * 8 + g;
                uint32_t b0 = Bs[brow * 36 + kk * 8 + tg];
                uint32_t b1 = Bs[brow * 36 + kk * 8 + 4 + tg];
                asm volatile(
                    "mma.sync.aligned.m16n8k16.row.col.f32.bf16.bf16.f32 "
                    "{%0,%1,%2,%3}, {%4,%5,%6,%7}, {%8,%9}, {%0,%1,%2,%3};\n"
                    : "+f"(acc[nt][0]), "+f"(acc[nt][1]), "+f"(acc[nt][2]), "+f"(acc[nt][3])
                    : "r"(a0), "r"(a1), "r"(a2), "r"(a3), "r"(b0), "r"(b1));
            }
        }
    }
    int row_lo = m0 + wm * 16 + g;
    int row_hi = row_lo + 8;
#pragma unroll
    for (int nt = 0; nt < 4; nt++) {
        int col = n0 + wn * 32 + nt * 8 + tg * 2;
        if (col < N) {
            float b0v = bias[col], b1v = bias[col + 1];
            *reinterpret_cast<float2*>(C + (size_t)row_lo * N + col) =
                make_float2(acc[nt][0] + b0v, acc[nt][1] + b1v);
            *reinterpret_cast<float2*>(C + (size_t)row_hi * N + col) =
                make_float2(acc[nt][2] + b0v, acc[nt][3] + b1v);
        }
    }
}

// ---------------- elementwise / reduction kernels ----------------
__global__ void k_build_xcat(const float* __restrict__ x_t, const float* __restrict__ ct_e,
                             float* __restrict__ xcat) {
    int idx = blockIdx.x * blockDim.x + threadIdx.x;
    int b = idx / 1280, j = idx - b * 1280;
    xcat[idx] = (j < Ee) ? x_t[b * Ee + j] : ct_e[b * 1024 + (j - Ee)];
}

__global__ void k_lstm_cell(const float* __restrict__ gates, const float* __restrict__ dec_c,
                            float* __restrict__ h_out, float* __restrict__ c_out,
                            float* __restrict__ sthat) {
    int idx = blockIdx.x * blockDim.x + threadIdx.x;
    int b = idx >> 9, j = idx & 511;
    const float* gr = gates + (size_t)b * 2048;
    float ig = sigf(gr[j]);
    float fg = sigf(gr[512 + j]);
    float gg = tanhf(gr[1024 + j]);
    float og = sigf(gr[1536 + j]);
    float c = fg * dec_c[idx] + ig * gg;
    float h = og * tanhf(c);
    h_out[idx] = h;
    c_out[idx] = c;
    sthat[(size_t)b * 1024 + j] = h;
    sthat[(size_t)b * 1024 + 512 + j] = c;
}

__global__ void k_enc_attn_norm(const float* __restrict__ et, const float* __restrict__ sum_t,
                                const float* __restrict__ mask, float* __restrict__ at,
                                float* __restrict__ sum_new) {
    int b = blockIdx.x;
    __shared__ float red[128];
    float local = 0.f;
    for (int n = threadIdx.x; n < Nn; n += 128) {
        float e = expf(et[b * Nn + n]);
        float st = sum_t[b * Nn + n];
        sum_new[b * Nn + n] = st + e;
        float a = (e / st) * mask[b * Nn + n];
        at[b * Nn + n] = a;
        local += a;
    }
    red[threadIdx.x] = local;
    __syncthreads();
    for (int s = 64; s > 0; s >>= 1) {
        if (threadIdx.x < s) red[threadIdx.x] += red[threadIdx.x + s];
        __syncthreads();
    }
    float inv = 1.f / red[0];
    for (int n = threadIdx.x; n < Nn; n += 128) at[b * Nn + n] *= inv;
}

__global__ void k_ctx_enc(const float* __restrict__ at, const float* __restrict__ enc,
                          float* __restrict__ ct) {
    int b = blockIdx.x, chunk = blockIdx.y;            // grid (256,4), 256 thr
    __shared__ float a_s[100];
    int n_start = chunk * 100;
    if (threadIdx.x < 100) a_s[threadIdx.x] = at[b * Nn + n_start + threadIdx.x];
    __syncthreads();
    float4 acc = make_float4(0.f, 0.f, 0.f, 0.f);
    int d4 = threadIdx.x;
    const float4* e4 = reinterpret_cast<const float4*>(enc + ((size_t)b * Nn + n_start) * 1024);
#pragma unroll 4
    for (int n = 0; n < 100; n++) {
        float4 x = e4[(size_t)n * 256 + d4];
        float a = a_s[n];
        acc.x += a * x.x; acc.y += a * x.y; acc.z += a * x.z; acc.w += a * x.w;
    }
    float* o = ct + (size_t)b * 1024 + d4 * 4;
    atomicAdd(o + 0, acc.x); atomicAdd(o + 1, acc.y);
    atomicAdd(o + 2, acc.z); atomicAdd(o + 3, acc.w);
}

__global__ void k_dec_attn(const float* __restrict__ etd, const float* __restrict__ prev_s,
                           float* __restrict__ ctd) {
    int b = blockIdx.x;
    __shared__ float a_s[Tt];
    if (threadIdx.x == 0) {
        float m = -1e30f;
        for (int t = 0; t < Tt; t++) m = fmaxf(m, etd[b * Tt + t]);
        float s = 0.f;
        for (int t = 0; t < Tt; t++) { float e = expf(etd[b * Tt + t] - m); a_s[t] = e; s += e; }
        float inv = 1.f / s;
        for (int t = 0; t < Tt; t++) a_s[t] *= inv;
    }
    __syncthreads();
    for (int h = threadIdx.x; h < Hh; h += 256) {
        float acc = 0.f;
        for (int t = 0; t < Tt; t++) acc += a_s[t] * prev_s[((size_t)b * Tt + t) * Hh + h];
        ctd[b * Hh + h] = acc;
    }
}

__global__ void k_pgen(const float* __restrict__ cte, const float* __restrict__ ctd,
                       const float* __restrict__ sthat, const float* __restrict__ x,
                       const float* __restrict__ pw, const float* __restrict__ pb,
                       float* __restrict__ pgen) {
    int b = blockIdx.x; int t = threadIdx.x;
    float acc = 0.f;
    for (int j = t; j < 1024; j += 128) acc += cte[b * 1024 + j] * pw[j];
    for (int j = t; j < 512;  j += 128) acc += ctd[b * 512 + j] * pw[1024 + j];
    for (int j = t; j < 1024; j += 128) acc += sthat[b * 1024 + j] * pw[1536 + j];
    for (int j = t; j < 256;  j += 128) acc += x[b * 256 + j] * pw[2560 + j];
    __shared__ float red[128];
    red[t] = acc;
    __syncthreads();
    for (int s = 64; s > 0; s >>= 1) { if (t < s) red[t] += red[t + s]; __syncthreads(); }
    if (t == 0) pgen[b] = sigf(red[0] + pb[0]);
}

__global__ void k_build_z(const float* __restrict__ h, const float* __restrict__ cte,
                          const float* __restrict__ ctd, float* __restrict__ z) {
    int idx = blockIdx.x * blockDim.x + threadIdx.x;
    int b = idx >> 11, j = idx & 2047;
    float v;
    if (j < 512)       v = h[b * 512 + j];
    else if (j < 1536) v = cte[b * 1024 + (j - 512)];
    else               v = ctd[b * 512 + (j - 1536)];
    z[idx] = v;
}

__global__ void k_softmax_stats(const float* __restrict__ logits,
                                float* __restrict__ rmax, float* __restrict__ rsum) {
    int b = blockIdx.x;
    __shared__ float red[256];
    float m = -1e30f;
    for (int v = threadIdx.x; v < Vv; v += 256) m = fmaxf(m, logits[(size_t)b * Vv + v]);
    red[threadIdx.x] = m;
    __syncthreads();
    for (int s = 128; s > 0; s >>= 1) {
        if (threadIdx.x < s) red[threadIdx.x] = fmaxf(red[threadIdx.x], red[threadIdx.x + s]);
        __syncthreads();
    }
    float mm = red[0];
    __syncthreads();
    float sum = 0.f;
    for (int v = threadIdx.x; v < Vv; v += 256) sum += expf(logits[(size_t)b * Vv + v] - mm);
    red[threadIdx.x] = sum;
    __syncthreads();
    for (int s = 128; s > 0; s >>= 1) {
        if (threadIdx.x < s) red[threadIdx.x] += red[threadIdx.x + s];
        __syncthreads();
    }
    if (threadIdx.x == 0) { rmax[b] = mm; rsum[b] = red[0]; }
}

__global__ void k_final_vocab(const float* __restrict__ logits, const float* __restrict__ rmax,
                              const float* __restrict__ rsum, const float* __restrict__ pgen,
                              const float* __restrict__ extra, float* __restrict__ out) {
    int idx = blockIdx.x * blockDim.x + threadIdx.x;
    if (idx >= Bq * (Vv + OOVn)) return;
    int b = idx / (Vv + OOVn);
    int v = idx - b * (Vv + OOVn);
    float val;
    if (v < Vv) val = pgen[b] * expf(logits[(size_t)b * Vv + v] - rmax[b]) / rsum[b];
    else        val = extra[(size_t)b * OOVn + (v - Vv)];
    out[idx] = val;
}

__global__ void k_scatter(const int* __restrict__ idxs, const float* __restrict__ at,
                          const float* __restrict__ pgen, float* __restrict__ out) {
    int i = blockIdx.x * blockDim.x + threadIdx.x;
    if (i >= Bq * Nn) return;
    int b = i / Nn;
    int v = idxs[i];
    atomicAdd(&out[(size_t)b * (Vv + OOVn) + v], (1.f - pgen[b]) * at[i]);
}

__global__ void k_build_prev_s(const float* __restrict__ prev_s, const float* __restrict__ h,
                               float* __restrict__ out) {
    int i = blockIdx.x * blockDim.x + threadIdx.x;
    if (i >= Bq * (Tt + 1) * Hh) return;
    int b = i / ((Tt + 1) * Hh);
    int r = i - b * ((Tt + 1) * Hh);
    int t = r / Hh, hh = r - t * Hh;
    out[i] = (t < Tt) ? prev_s[((size_t)b * Tt + t) * Hh + hh] : h[b * Hh + hh];
}

// ---------------- host launcher ----------------
extern "C" void kernel_launch(void* const* d_in, const int* in_sizes, int n_in,
                              void* d_out, int out_size) {
    const float* x_t          = (const float*)d_in[0];
    const float* dec_h        = (const float*)d_in[1];
    const float* dec_c        = (const float*)d_in[2];
    const float* enc_out      = (const float*)d_in[3];
    const float* enc_mask     = (const float*)d_in[4];
    const float* ct_e         = (const float*)d_in[5];
    const float* extra_zeros  = (const float*)d_in[6];
    const int*   ext_vocab    = (const int*)d_in[7];
    const float* sum_temporal = (const float*)d_in[8];
    const float* prev_s       = (const float*)d_in[9];
    const float* x_input_w    = (const float*)d_in[10];
    const float* x_input_b    = (const float*)d_in[11];
    const float* lstm_w_ih    = (const float*)d_in[12];
    const float* lstm_w_hh    = (const float*)d_in[13];
    const float* lstm_b_ih    = (const float*)d_in[14];
    const float* lstm_b_hh    = (const float*)d_in[15];
    const float* pgen_w       = (const float*)d_in[16];
    const float* pgen_b       = (const float*)d_in[17];
    const float* V_w          = (const float*)d_in[18];
    const float* V_b          = (const float*)d_in[19];
    const float* V1_w         = (const float*)d_in[20];
    const float* V1_b         = (const float*)d_in[21];
    const float* Wh_w         = (const float*)d_in[22];
    const float* Ws_w         = (const float*)d_in[23];
    const float* Ws_b         = (const float*)d_in[24];
    const float* v_w          = (const float*)d_in[25];
    const float* Wprev_w      = (const float*)d_in[26];
    const float* Wsd_w        = (const float*)d_in[27];
    const float* Wsd_b        = (const float*)d_in[28];
    const float* vd_w         = (const float*)d_in[29];

    float* out = (float*)d_out;
    float* o_final = out + O_FINAL;
    float* o_h     = out + O_H;
    float* o_c     = out + O_C;
    float* o_cte   = out + O_CTE;
    float* o_sum   = out + O_SUM;
    float* o_prevs = out + O_PREVS;

    void* p = nullptr;
    cudaGetSymbolAddress(&p, g_scratch);
    float* S = (float*)p;
    cudaGetSymbolAddress(&p, g_bf);
    __nv_bfloat16* BF = (__nv_bfloat16*)p;

    float* s_xcat  = S + F_XCAT;
    float* s_x     = S + F_X;
    float* s_gates = S + F_GATES;
    float* s_sthat = S + F_STHAT;
    float* s_senc  = S + F_SENC;
    float* s_sdec  = S + F_SDEC;
    float* s_et    = S + F_ET;
    float* s_at    = S + F_AT;
    float* s_etd   = S + F_ETD;
    float* s_ctd   = S + F_CTD;
    float* s_pgen  = S + F_PGEN;
    float* s_z     = S + F_Z;
    float* s_outv  = S + F_OUTV;
    float* s_log   = S + F_LOGITS;
    float* s_rmax  = S + F_RMAX;
    float* s_rsum  = S + F_RSUM;

    __nv_bfloat16* bf_wh    = BF + B_WH;
    __nv_bfloat16* bf_wprev = BF + B_WPREV;
    __nv_bfloat16* bf_v1    = BF + B_V1;

    // dynamic smem: A full-K + 2 x (64 x 68 u32) B buffers
    const int SMEM_ENC = (64 * (1024 / 2 + 4) + 2 * 64 * 68) * 4;   // 166912
    const int SMEM_DEC = (64 * (512 / 2 + 4) + 2 * 64 * 68) * 4;    // 101376
    const int SMEM_LOG = (64 * (512 / 2 + 4) + 64 * 36) * 4;        // 75776
    cudaFuncSetAttribute(k_fused_score<1024, 1024, 400>,
                         cudaFuncAttributeMaxDynamicSharedMemorySize, SMEM_ENC);
    cudaFuncSetAttribute(k_fused_score<512, 512, 49>,
                         cudaFuncAttributeMaxDynamicSharedMemorySize, SMEM_DEC);
    cudaFuncSetAttribute(k_gemm_mma_logits,
                         cudaFuncAttributeMaxDynamicSharedMemorySize, SMEM_LOG);

    // 0) weight conversions to bf16
    k_cvt_bf16<<<2048, 256>>>(Wh_w, bf_wh, 1024 * 1024);
    k_cvt_bf16<<<1024, 256>>>(Wprev_w, bf_wprev, 512 * 512);
    k_cvt_bf16<<<4096, 256>>>(V1_w, bf_v1, Vv * 512);

    // 1) x = [x_t | ct_e] @ x_input_w^T + b
    k_build_xcat<<<(256 * 1280) / 256, 256>>>(x_t, ct_e, s_xcat);
    k_gemm_f32<<<dim3(4, 4), 256>>>(s_xcat, x_input_w, x_input_b, s_x, 256, 256, 1280, 0);

    // 2) LSTM gates + cell
    k_gemm_f32<<<dim3(4, 32), 256>>>(s_x, lstm_w_ih, lstm_b_ih, s_gates, 256, 2048, 256, 0);
    k_gemm_f32<<<dim3(4, 32), 256>>>(dec_h, lstm_w_hh, lstm_b_hh, s_gates, 256, 2048, 512, 1);
    k_lstm_cell<<<512, 256>>>(s_gates, dec_c, o_h, o_c, s_sthat);

    // 3) encoder attention
    k_gemm_f32<<<dim3(4, 16), 256>>>(s_sthat, Ws_w, Ws_b, s_senc, 256, 1024, 1024, 0);
    cudaMemsetAsync(s_et, 0, 102400 * sizeof(float));
    k_fused_score<1024, 1024, 400><<<1600, 256, SMEM_ENC>>>(enc_out, bf_wh, s_senc, v_w, s_et);
    k_enc_attn_norm<<<256, 128>>>(s_et, sum_temporal, enc_mask, s_at, o_sum);
    cudaMemsetAsync(o_cte, 0, 262144 * sizeof(float));
    k_ctx_enc<<<dim3(256, 4), 256>>>(s_at, enc_out, o_cte);

    // 4) decoder intra-attention
    k_gemm_f32<<<dim3(4, 8), 256>>>(o_h, Wsd_w, Wsd_b, s_sdec, 256, 512, 512, 0);
    cudaMemsetAsync(s_etd, 0, 12544 * sizeof(float));
    k_fused_score<512, 512, 49><<<196, 256, SMEM_DEC>>>(prev_s, bf_wprev, s_sdec, vd_w, s_etd);
    k_dec_attn<<<256, 256>>>(s_etd, prev_s, s_ctd);

    // 5) pointer-generator head
    k_pgen<<<256, 128>>>(o_cte, s_ctd, s_sthat, s_x, pgen_w, pgen_b, s_pgen);
    k_build_z<<<(256 * 2048) / 256, 256>>>(o_h, o_cte, s_ctd, s_z);
    k_gemm_f32<<<dim3(4, 8), 256>>>(s_z, V_w, V_b, s_outv, 256, 512, 2048, 0);
    k_gemm_mma_logits<<<dim3(4, 782), 256, SMEM_LOG>>>(s_outv, bf_v1, V1_b, s_log, Vv);
    k_softmax_stats<<<256, 256>>>(s_log, s_rmax, s_rsum);

    // 6) final distribution
    k_final_vocab<<<(Bq * (Vv + OOVn) + 255) / 256, 256>>>(s_log, s_rmax, s_rsum, s_pgen,
                                                           extra_zeros, o_final);
    k_scatter<<<(Bq * Nn + 255) / 256, 256>>>(ext_vocab, s_at, s_pgen, o_final);

    // 7) prev_s_new
    k_build_prev_s<<<(Bq * (Tt + 1) * Hh + 255) / 256, 256>>>(prev_s, o_h, o_prevs);
}